// round 12
// baseline (speedup 1.0000x reference)
#include <cuda_runtime.h>
#include <cstdint>
#include <cstddef>

#define BATCH 64
#define CIN   64
#define COUT  64
#define MODES 16
#define NRES  8192
#define NH    4096   // NRES/2
#define NQ    2048   // NRES/4 — quarter-symmetry-reduced n range

typedef unsigned long long u64;

// Persistent device scratch (allocation-free rule: __device__ globals)
// Twiddles for n in [0,2048], modes EVEN/ODD-reordered:
//   slot s<8 -> m=2s, s>=8 -> m=2(s-8)+1. Each = (cos(2*pi*m*n/N), -sin(...)).
__device__ __align__(16) float2 g_tw[2080][MODES];          // ~266 KB, L2-resident
__device__ __align__(16) float2 g_Xp[4][BATCH][CIN][MODES]; // fwd n-partials, 2 MB
__device__ __align__(16) float2 g_Y [BATCH][COUT][MODES];   // mixed+scaled, slot order

// ---- packed f32x2 helpers (sm_100+) ----
__device__ __forceinline__ void ffma2(u64 &d, u64 a, u64 b) {
    asm("fma.rn.f32x2 %0, %1, %2, %0;" : "+l"(d) : "l"(a), "l"(b));
}
__device__ __forceinline__ void fadd2(u64 &d, u64 a) {
    asm("add.rn.f32x2 %0, %0, %1;" : "+l"(d) : "l"(a));
}
__device__ __forceinline__ u64 pk2(float lo, float hi) {
    u64 r; asm("mov.b64 %0, {%1, %2};" : "=l"(r) : "f"(lo), "f"(hi)); return r;
}
__device__ __forceinline__ void upk2(u64 v, float &lo, float &hi) {
    asm("mov.b64 {%0, %1}, %2;" : "=f"(lo), "=f"(hi) : "l"(v));
}
__device__ __forceinline__ int mslot(int m) { return ((m & 1) << 3) | (m >> 1); }

// ---- cp.async helpers ----
__device__ __forceinline__ uint32_t sptr(const void* p) {
    return (uint32_t)__cvta_generic_to_shared(p);
}
__device__ __forceinline__ void cpa16(uint32_t dst, const void* src) {
    asm volatile("cp.async.cg.shared.global [%0], [%1], 16;" :: "r"(dst), "l"(src));
}
__device__ __forceinline__ void cpa_commit() {
    asm volatile("cp.async.commit_group;" ::: "memory");
}
__device__ __forceinline__ void cpa_wait0() {
    asm volatile("cp.async.wait_group 0;" ::: "memory");
}
__device__ __forceinline__ void cpa_wait1() {
    asm volatile("cp.async.wait_group 1;" ::: "memory");
}

// ------------------------------------------------------------------
// Kernel 1: twiddle table, n in [0,2048].
// ------------------------------------------------------------------
__global__ void tw_kernel() {
    int idx = blockIdx.x * blockDim.x + threadIdx.x;
    if (idx >= 2049 * 16) return;
    int n = idx >> 4, m = idx & 15;
    int r = (n * m) & (NRES - 1);
    float s, c;
    sincospif((float)r * (1.0f / NH), &s, &c);
    g_tw[n][mslot(m)] = make_float2(c, -s);
}

// ------------------------------------------------------------------
// Kernel 2: quarter-folded forward DFT — depth-2 cp.async pipeline.
// Grid 256 = (b:64, q:4). Block 256 thr = 8 warps; 32 chunks of 16 n.
// Per iter: issue stage(ch+1) -> wait_group 1 (stage ch done, ch+1 in
// flight across the WHOLE iter) -> sync -> fold+tw-snapshot -> sync ->
// compute. Raw tiles double-buffered; twc snapshot kills the tws WAR
// hazard; reduction scratch in a disjoint smem region (no uvq race).
// ------------------------------------------------------------------
// smem layout (bytes):
#define SM_AS   0        // [2][64][16] float   8192
#define SM_BS   8192     // [2][64][16] float   8192
#define SM_MS   16384    // [2][64][20] float  10240
#define SM_MBS  26624    // [2][64][20] float  10240
#define SM_TWS  36864    // [2][16][16] u64     4096
#define SM_TWC  40960    // [16][16]    u64     2048
#define SM_UVQ  43008    // [64][17]    float4 17408
#define SM_TOT  60416

__global__ void __launch_bounds__(256, 2) fwd_kernel(const float* __restrict__ x) {
    __shared__ __align__(16) char SM[SM_TOT];
    float*  As  = (float*) (SM + SM_AS);
    float*  Bs  = (float*) (SM + SM_BS);
    float*  Ms  = (float*) (SM + SM_MS);
    float*  MBs = (float*) (SM + SM_MBS);
    u64*    tws = (u64*)  (SM + SM_TWS);
    u64*    twc = (u64*)  (SM + SM_TWC);
    float4* uvq = (float4*)(SM + SM_UVQ);

    int b = blockIdx.x >> 2, q = blockIdx.x & 3;
    int tid = threadIdx.x, w = tid >> 5, l = tid & 31;
    const float* xb = x + (size_t)b * CIN * NRES;
    int base = q << 9;                             // 512 staged n per block

    u64 acc[32];                                   // [0..15]: i=l, [16..31]: i=l+32
    #pragma unroll
    for (int s = 0; s < 32; ++s) acc[s] = 0ull;

    auto stage = [&](int nb, int par) {
        {   // A, B: 64 rows x 16 cols (stride 16 floats, 16B-aligned rows)
            int row = tid >> 2, u4 = (tid & 3) << 2;
            const float* p = xb + (size_t)row * NRES + nb + u4;
            cpa16(sptr(As + (par << 10) + row * 16 + u4), p);
            cpa16(sptr(Bs + (par << 10) + row * 16 + u4), p + NH);
        }
        {   // mirror strips: 64 rows x 20 floats (fwd-contig; reversal by index)
            int mbase = NH - nb - 16;
            for (int idx = tid; idx < 320; idx += 256) {
                int r2 = idx / 5, g4 = (idx % 5) << 2;
                const float* pm = xb + (size_t)r2 * NRES + mbase + g4;
                cpa16(sptr(Ms  + par * 1280 + r2 * 20 + g4), pm);
                cpa16(sptr(MBs + par * 1280 + r2 * 20 + g4), pm + NH);
            }
        }
        if (tid < 128)                              // tw chunk: 16 n x 128B = 2KB
            cpa16(sptr((char*)(tws + (par << 8)) + (tid << 4)),
                  (const char*)&g_tw[nb][0] + (tid << 4));
    };

    stage(base, 0);
    cpa_commit();

    for (int ch = 0; ch < 32; ++ch) {
        int par = ch & 1;
        if (ch < 31) {                              // keep next stage in flight
            stage(base + ((ch + 1) << 4), par ^ 1);
            cpa_commit();
            cpa_wait1();                            // stage(ch) done; (ch+1) pending
        } else {
            cpa_wait0();
        }
        __syncthreads();                            // raw chunk visible to all

        // fold raw -> uvq, plus twiddle snapshot tws[par] -> twc
        {
            int row = tid >> 2, c4 = (tid & 3) << 2;
            const float* ap  = As  + (par << 10) + row * 16;
            const float* bp  = Bs  + (par << 10) + row * 16;
            const float* mp  = Ms  + par * 1280  + row * 20;
            const float* mbp = MBs + par * 1280  + row * 20;
            float4 a  = *(const float4*)(ap + c4);
            float4 bb = *(const float4*)(bp + c4);
            float av[4] = {a.x, a.y, a.z, a.w};
            float bv[4] = {bb.x, bb.y, bb.z, bb.w};
            int nb = base + (ch << 4);
            #pragma unroll
            for (int j = 0; j < 4; ++j) {
                int col = c4 + j;
                float m_  = mp [16 - col];          // mirror via indexing
                float mb_ = mbp[16 - col];
                if (nb == 0 && col == 0) { m_ = 0.0f; mb_ = 0.0f; } // n=0: no partner
                float u  = av[j] + bv[j], v  = av[j] - bv[j];
                float up = m_ + mb_,      vp = m_ - mb_;
                uvq[row * 17 + col] = make_float4(u + up, u - up, v - vp, v + vp);
            }
            twc[tid] = tws[(par << 8) + tid];
        }
        __syncthreads();                            // uvq + twc ready

        // compute: warp w owns cols {2w, 2w+1}; lanes = i and i+32
        #pragma unroll
        for (int cc = 0; cc < 2; ++cc) {
            int c = (w << 1) | cc;
            float4 q0 = uvq[l * 17 + c], q1 = uvq[(l + 32) * 17 + c];
            u64 pe0 = pk2(q0.x, q0.y), po0 = pk2(q0.z, q0.w);
            u64 pe1 = pk2(q1.x, q1.y), po1 = pk2(q1.z, q1.w);
            const ulonglong2* tp = (const ulonglong2*)(twc + c * 16);
            #pragma unroll
            for (int m2 = 0; m2 < 4; ++m2) {        // even slots
                ulonglong2 t = tp[m2];
                ffma2(acc[2 * m2],      t.x, pe0);
                ffma2(acc[2 * m2 + 1],  t.y, pe0);
                ffma2(acc[16 + 2 * m2], t.x, pe1);
                ffma2(acc[17 + 2 * m2], t.y, pe1);
            }
            #pragma unroll
            for (int m2 = 4; m2 < 8; ++m2) {        // odd slots
                ulonglong2 t = tp[m2];
                ffma2(acc[2 * m2],      t.x, po0);
                ffma2(acc[2 * m2 + 1],  t.y, po0);
                ffma2(acc[16 + 2 * m2], t.x, po1);
                ffma2(acc[17 + 2 * m2], t.y, po1);
            }
        }
        // next iteration's first __syncthreads orders uvq/twc overwrite
    }

    // self-paired n=2048 contribution (added once, by warp 0 of q==0 blocks)
    if (q == 0 && w == 0) {
        const float* p0 = xb + (size_t)l * NRES;
        const float* p1 = xb + (size_t)(l + 32) * NRES;
        float u0 = p0[NQ] + p0[NQ + NH], v0 = p0[NQ] - p0[NQ + NH];
        float u1 = p1[NQ] + p1[NQ + NH], v1 = p1[NQ] - p1[NQ + NH];
        u64 pe0 = pk2(u0, u0), po0 = pk2(v0, v0);
        u64 pe1 = pk2(u1, u1), po1 = pk2(v1, v1);
        const ulonglong2* tp = (const ulonglong2*)&g_tw[NQ][0];
        #pragma unroll
        for (int m2 = 0; m2 < 4; ++m2) {
            ulonglong2 t = tp[m2];
            ffma2(acc[2 * m2],      t.x, pe0); ffma2(acc[2 * m2 + 1],  t.y, pe0);
            ffma2(acc[16 + 2 * m2], t.x, pe1); ffma2(acc[17 + 2 * m2], t.y, pe1);
        }
        #pragma unroll
        for (int m2 = 4; m2 < 8; ++m2) {
            ulonglong2 t = tp[m2];
            ffma2(acc[2 * m2],      t.x, po0); ffma2(acc[2 * m2 + 1],  t.y, po0);
            ffma2(acc[16 + 2 * m2], t.x, po1); ffma2(acc[17 + 2 * m2], t.y, po1);
        }
    }

    // cross-warp tree reduction, two 16-acc phases.
    // Scratch = SM[0..16K) (As/Bs region) — DISJOINT from uvq/twc (no race).
    u64* red = (u64*)SM;
    #pragma unroll
    for (int g = 0; g < 32; g += 16) {
        for (int half = 4; half > 0; half >>= 1) {
            if (w >= half && w < (half << 1)) {
                #pragma unroll
                for (int m = 0; m < 16; ++m)
                    red[((((w - half) << 4) + m) << 5) + l] = acc[g + m];
            }
            __syncthreads();
            if (w < half) {
                #pragma unroll
                for (int m = 0; m < 16; ++m)
                    fadd2(acc[g + m], red[(((w << 4) + m) << 5) + l]);
            }
            __syncthreads();
        }
    }
    if (w == 0) {
        u64* Xp = (u64*)&g_Xp[q][b][0][0];
        #pragma unroll
        for (int m = 0; m < 16; ++m) {
            Xp[l * 16 + m]        = acc[m];
            Xp[(l + 32) * 16 + m] = acc[16 + m];
        }
    }
}

// ------------------------------------------------------------------
// Kernel 3: sum 4 fwd partials + complex mode mix + irfft scale.
// ------------------------------------------------------------------
__global__ void __launch_bounds__(512) mix_kernel(const float* __restrict__ wr,
                                                  const float* __restrict__ wi) {
    __shared__ __align__(16) float2 Xs[CIN][MODES];   // 8 KB, slot order
    int b = blockIdx.x >> 1, oh = blockIdx.x & 1;
    int tid = threadIdx.x;
    const int STRIDE = BATCH * CIN * MODES;
    for (int t = tid; t < CIN * MODES; t += 512) {
        const float2* p = &((const float2*)g_Xp)[(size_t)b * CIN * MODES + t];
        float sx = 0.f, sy = 0.f;
        #pragma unroll
        for (int k = 0; k < 4; ++k) {
            float2 a = p[(size_t)k * STRIDE];
            sx += a.x; sy += a.y;
        }
        ((float2*)Xs)[t] = make_float2(sx, sy);
    }
    __syncthreads();
    int o = (oh << 5) + (tid >> 4), m = tid & 15, s = mslot(m);
    float yr = 0.f, yi = 0.f;
    #pragma unroll 4
    for (int i = 0; i < CIN; ++i) {
        float2 xv = Xs[i][s];
        float a = wr[(i * COUT + o) * MODES + m];
        float c = wi[(i * COUT + o) * MODES + m];
        yr = fmaf(xv.x, a, yr); yr = fmaf(-xv.y, c, yr);
        yi = fmaf(xv.x, c, yi); yi = fmaf(xv.y, a, yi);
    }
    float sc = (m == 0 ? 1.0f : 2.0f) * (1.0f / NRES);
    g_Y[b][o][s] = make_float2(yr * sc, yi * sc);
}

// ------------------------------------------------------------------
// Kernel 4: quarter-folded inverse, 2 n per thread (n0, n0+1).
// Grid 512 = (b:64, q:8), block 128, lb(128,4) -> one wave.
// 8 broadcast Y-LDS feed 32 ffma2; forward pair stores are STG.64.
// ------------------------------------------------------------------
__global__ void __launch_bounds__(128, 4) inv_kernel(float* __restrict__ out) {
    __shared__ __align__(16) u64 Ysh[COUT][MODES];   // 8 KB, slot order
    int b = blockIdx.x >> 3, q = blockIdx.x & 7;
    int tid = threadIdx.x;
    const u64* Yg = (const u64*)g_Y + (size_t)b * COUT * MODES;
    #pragma unroll
    for (int k = 0; k < 8; ++k) ((u64*)Ysh)[tid + k * 128] = Yg[tid + k * 128];
    __syncthreads();

    int n0 = (q << 8) + (tid << 1);                  // this thread: n0, n0+1
    u64 twA[16], twB[16];
    {
        const ulonglong2* tp = (const ulonglong2*)&g_tw[n0][0];
        #pragma unroll
        for (int m2 = 0; m2 < 8; ++m2) {
            ulonglong2 t = tp[m2];
            twA[2 * m2] = t.x; twA[2 * m2 + 1] = t.y;
        }
        tp = (const ulonglong2*)&g_tw[n0 + 1][0];
        #pragma unroll
        for (int m2 = 0; m2 < 8; ++m2) {
            ulonglong2 t = tp[m2];
            twB[2 * m2] = t.x; twB[2 * m2 + 1] = t.y;
        }
    }
    float* pb = out + (size_t)b * COUT * NRES;

    #pragma unroll 2
    for (int o = 0; o < COUT; ++o) {
        const ulonglong2* yp = (const ulonglong2*)&Ysh[o][0];
        u64 e0 = 0ull, od0 = 0ull, e1 = 0ull, od1 = 0ull;
        #pragma unroll
        for (int m2 = 0; m2 < 4; ++m2) {             // even slots
            ulonglong2 y = yp[m2];
            ffma2(e0, y.x, twA[2 * m2]); ffma2(e0, y.y, twA[2 * m2 + 1]);
            ffma2(e1, y.x, twB[2 * m2]); ffma2(e1, y.y, twB[2 * m2 + 1]);
        }
        #pragma unroll
        for (int m2 = 4; m2 < 8; ++m2) {             // odd slots
            ulonglong2 y = yp[m2];
            ffma2(od0, y.x, twA[2 * m2]); ffma2(od0, y.y, twA[2 * m2 + 1]);
            ffma2(od1, y.x, twB[2 * m2]); ffma2(od1, y.y, twB[2 * m2 + 1]);
        }
        float pe, qe, po, qo;
        upk2(e0,  pe, qe); float S0 = pe + qe, D0 = pe - qe;
        upk2(od0, po, qo); float T0 = po + qo, U0 = qo - po;
        upk2(e1,  pe, qe); float S1 = pe + qe, D1 = pe - qe;
        upk2(od1, po, qo); float T1 = po + qo, U1 = qo - po;
        float* p = pb + (size_t)o * NRES;
        *(float2*)(p + n0)      = make_float2(S0 + T0, S1 + T1);
        *(float2*)(p + n0 + NH) = make_float2(S0 - T0, S1 - T1);
        if (n0) {
            p[NH - n0]       = D0 + U0;
            p[NH - n0 - 1]   = D1 + U1;
            p[NRES - n0]     = D0 - U0;
            p[NRES - n0 - 1] = D1 - U1;
        } else {                                     // n=0 has no mirror; n=1 does
            p[NH - 1]   = D1 + U1;
            p[NRES - 1] = D1 - U1;
        }
    }

    // self-paired n=2048 outputs — q==0, one o per thread
    if (q == 0 && tid < COUT) {
        int o = tid;
        const ulonglong2* tp = (const ulonglong2*)&g_tw[NQ][0];
        const ulonglong2* yp = (const ulonglong2*)&Ysh[o][0];
        u64 e = 0ull, od = 0ull;
        #pragma unroll
        for (int m2 = 0; m2 < 4; ++m2) {
            ulonglong2 t = tp[m2]; ulonglong2 y = yp[m2];
            ffma2(e, y.x, t.x); ffma2(e, y.y, t.y);
        }
        #pragma unroll
        for (int m2 = 4; m2 < 8; ++m2) {
            ulonglong2 t = tp[m2]; ulonglong2 y = yp[m2];
            ffma2(od, y.x, t.x); ffma2(od, y.y, t.y);
        }
        float pe, qe, po, qo;
        upk2(e, pe, qe); upk2(od, po, qo);
        float E = pe + qe, O = po + qo;
        float* p = pb + (size_t)o * NRES;
        p[NQ]      = E + O;
        p[NQ + NH] = E - O;
    }
}

// ------------------------------------------------------------------
extern "C" void kernel_launch(void* const* d_in, const int* in_sizes, int n_in,
                              void* d_out, int out_size) {
    (void)in_sizes; (void)n_in; (void)out_size;
    const float* x  = (const float*)d_in[0];   // [64,64,8192]
    const float* wr = (const float*)d_in[1];   // [64,64,16]
    const float* wi = (const float*)d_in[2];   // [64,64,16]
    float* out = (float*)d_out;                // [64,64,8192]

    tw_kernel <<<129, 256>>>();
    fwd_kernel<<<256, 256>>>(x);
    mix_kernel<<<128, 512>>>(wr, wi);
    inv_kernel<<<512, 128>>>(out);
}

// round 13
// speedup vs baseline: 1.0110x; 1.0110x over previous
#include <cuda_runtime.h>
#include <cstdint>
#include <cstddef>

#define BATCH 64
#define CIN   64
#define COUT  64
#define MODES 16
#define NRES  8192
#define NH    4096   // NRES/2
#define NQ    2048   // NRES/4 — quarter-symmetry-reduced n range

typedef unsigned long long u64;

// Persistent device scratch (allocation-free rule: __device__ globals)
// Twiddles for n in [0,2048], modes EVEN/ODD-reordered:
//   slot s<8 -> m=2s, s>=8 -> m=2(s-8)+1. Each = (cos(2*pi*m*n/N), -sin(...)).
__device__ __align__(16) float2 g_tw[2080][MODES];          // ~266 KB, L2-resident
__device__ __align__(16) float2 g_Xp[4][BATCH][CIN][MODES]; // fwd n-partials, 2 MB
__device__ __align__(16) float2 g_Y [BATCH][COUT][MODES];   // mixed+scaled, slot order

// ---- packed f32x2 helpers (sm_100+) ----
__device__ __forceinline__ void ffma2(u64 &d, u64 a, u64 b) {
    asm("fma.rn.f32x2 %0, %1, %2, %0;" : "+l"(d) : "l"(a), "l"(b));
}
__device__ __forceinline__ void fadd2(u64 &d, u64 a) {
    asm("add.rn.f32x2 %0, %0, %1;" : "+l"(d) : "l"(a));
}
__device__ __forceinline__ u64 pk2(float lo, float hi) {
    u64 r; asm("mov.b64 %0, {%1, %2};" : "=l"(r) : "f"(lo), "f"(hi)); return r;
}
__device__ __forceinline__ void upk2(u64 v, float &lo, float &hi) {
    asm("mov.b64 {%0, %1}, %2;" : "=f"(lo), "=f"(hi) : "l"(v));
}
__device__ __forceinline__ int mslot(int m) { return ((m & 1) << 3) | (m >> 1); }

// ---- cp.async helpers ----
__device__ __forceinline__ uint32_t sptr(const void* p) {
    return (uint32_t)__cvta_generic_to_shared(p);
}
__device__ __forceinline__ void cpa16(uint32_t dst, const void* src) {
    asm volatile("cp.async.cg.shared.global [%0], [%1], 16;" :: "r"(dst), "l"(src));
}
__device__ __forceinline__ void cpa_commit() {
    asm volatile("cp.async.commit_group;" ::: "memory");
}
__device__ __forceinline__ void cpa_wait0() {
    asm volatile("cp.async.wait_group 0;" ::: "memory");
}
__device__ __forceinline__ void cpa_wait1() {
    asm volatile("cp.async.wait_group 1;" ::: "memory");
}

// ------------------------------------------------------------------
// Kernel 1: twiddle table, n in [0,2048].
// ------------------------------------------------------------------
__global__ void tw_kernel() {
    int idx = blockIdx.x * blockDim.x + threadIdx.x;
    if (idx >= 2049 * 16) return;
    int n = idx >> 4, m = idx & 15;
    int r = (n * m) & (NRES - 1);
    float s, c;
    sincospif((float)r * (1.0f / NH), &s, &c);
    g_tw[n][mslot(m)] = make_float2(c, -s);
}

// ------------------------------------------------------------------
// Kernel 2: quarter-folded forward DFT — depth-2 cp.async pipeline.
// Grid 256 = (b:64, q:4). Block 256 thr = 8 warps; 32 chunks of 16 n.
// Per iter: issue stage(ch+1) -> wait_group 1 (stage ch done, ch+1 in
// flight across the WHOLE iter) -> sync -> fold+tw-snapshot -> sync ->
// compute. Raw tiles double-buffered; twc snapshot kills the tws WAR
// hazard; reduction scratch in a disjoint smem region (no uvq race).
// ------------------------------------------------------------------
// smem layout (bytes):
#define SM_AS   0        // [2][64][16] float   8192
#define SM_BS   8192     // [2][64][16] float   8192
#define SM_MS   16384    // [2][64][20] float  10240
#define SM_MBS  26624    // [2][64][20] float  10240
#define SM_TWS  36864    // [2][16][16] u64     4096
#define SM_TWC  40960    // [16][16]    u64     2048
#define SM_UVQ  43008    // [64][17]    float4 17408
#define SM_TOT  60416

__global__ void __launch_bounds__(256, 2) fwd_kernel(const float* __restrict__ x) {
    __shared__ __align__(16) char SM[SM_TOT];
    float*  As  = (float*) (SM + SM_AS);
    float*  Bs  = (float*) (SM + SM_BS);
    float*  Ms  = (float*) (SM + SM_MS);
    float*  MBs = (float*) (SM + SM_MBS);
    u64*    tws = (u64*)  (SM + SM_TWS);
    u64*    twc = (u64*)  (SM + SM_TWC);
    float4* uvq = (float4*)(SM + SM_UVQ);

    int b = blockIdx.x >> 2, q = blockIdx.x & 3;
    int tid = threadIdx.x, w = tid >> 5, l = tid & 31;
    const float* xb = x + (size_t)b * CIN * NRES;
    int base = q << 9;                             // 512 staged n per block

    u64 acc[32];                                   // [0..15]: i=l, [16..31]: i=l+32
    #pragma unroll
    for (int s = 0; s < 32; ++s) acc[s] = 0ull;

    auto stage = [&](int nb, int par) {
        {   // A, B: 64 rows x 16 cols (stride 16 floats, 16B-aligned rows)
            int row = tid >> 2, u4 = (tid & 3) << 2;
            const float* p = xb + (size_t)row * NRES + nb + u4;
            cpa16(sptr(As + (par << 10) + row * 16 + u4), p);
            cpa16(sptr(Bs + (par << 10) + row * 16 + u4), p + NH);
        }
        {   // mirror strips: 64 rows x 20 floats (fwd-contig; reversal by index)
            int mbase = NH - nb - 16;
            for (int idx = tid; idx < 320; idx += 256) {
                int r2 = idx / 5, g4 = (idx % 5) << 2;
                const float* pm = xb + (size_t)r2 * NRES + mbase + g4;
                cpa16(sptr(Ms  + par * 1280 + r2 * 20 + g4), pm);
                cpa16(sptr(MBs + par * 1280 + r2 * 20 + g4), pm + NH);
            }
        }
        if (tid < 128)                              // tw chunk: 16 n x 128B = 2KB
            cpa16(sptr((char*)(tws + (par << 8)) + (tid << 4)),
                  (const char*)&g_tw[nb][0] + (tid << 4));
    };

    stage(base, 0);
    cpa_commit();

    for (int ch = 0; ch < 32; ++ch) {
        int par = ch & 1;
        if (ch < 31) {                              // keep next stage in flight
            stage(base + ((ch + 1) << 4), par ^ 1);
            cpa_commit();
            cpa_wait1();                            // stage(ch) done; (ch+1) pending
        } else {
            cpa_wait0();
        }
        __syncthreads();                            // raw chunk visible to all

        // fold raw -> uvq, plus twiddle snapshot tws[par] -> twc
        {
            int row = tid >> 2, c4 = (tid & 3) << 2;
            const float* ap  = As  + (par << 10) + row * 16;
            const float* bp  = Bs  + (par << 10) + row * 16;
            const float* mp  = Ms  + par * 1280  + row * 20;
            const float* mbp = MBs + par * 1280  + row * 20;
            float4 a  = *(const float4*)(ap + c4);
            float4 bb = *(const float4*)(bp + c4);
            float av[4] = {a.x, a.y, a.z, a.w};
            float bv[4] = {bb.x, bb.y, bb.z, bb.w};
            int nb = base + (ch << 4);
            #pragma unroll
            for (int j = 0; j < 4; ++j) {
                int col = c4 + j;
                float m_  = mp [16 - col];          // mirror via indexing
                float mb_ = mbp[16 - col];
                if (nb == 0 && col == 0) { m_ = 0.0f; mb_ = 0.0f; } // n=0: no partner
                float u  = av[j] + bv[j], v  = av[j] - bv[j];
                float up = m_ + mb_,      vp = m_ - mb_;
                uvq[row * 17 + col] = make_float4(u + up, u - up, v - vp, v + vp);
            }
            twc[tid] = tws[(par << 8) + tid];
        }
        __syncthreads();                            // uvq + twc ready

        // compute: warp w owns cols {2w, 2w+1}; lanes = i and i+32
        #pragma unroll
        for (int cc = 0; cc < 2; ++cc) {
            int c = (w << 1) | cc;
            float4 q0 = uvq[l * 17 + c], q1 = uvq[(l + 32) * 17 + c];
            u64 pe0 = pk2(q0.x, q0.y), po0 = pk2(q0.z, q0.w);
            u64 pe1 = pk2(q1.x, q1.y), po1 = pk2(q1.z, q1.w);
            const ulonglong2* tp = (const ulonglong2*)(twc + c * 16);
            #pragma unroll
            for (int m2 = 0; m2 < 4; ++m2) {        // even slots
                ulonglong2 t = tp[m2];
                ffma2(acc[2 * m2],      t.x, pe0);
                ffma2(acc[2 * m2 + 1],  t.y, pe0);
                ffma2(acc[16 + 2 * m2], t.x, pe1);
                ffma2(acc[17 + 2 * m2], t.y, pe1);
            }
            #pragma unroll
            for (int m2 = 4; m2 < 8; ++m2) {        // odd slots
                ulonglong2 t = tp[m2];
                ffma2(acc[2 * m2],      t.x, po0);
                ffma2(acc[2 * m2 + 1],  t.y, po0);
                ffma2(acc[16 + 2 * m2], t.x, po1);
                ffma2(acc[17 + 2 * m2], t.y, po1);
            }
        }
        // next iteration's first __syncthreads orders uvq/twc overwrite
    }

    // self-paired n=2048 contribution (added once, by warp 0 of q==0 blocks)
    if (q == 0 && w == 0) {
        const float* p0 = xb + (size_t)l * NRES;
        const float* p1 = xb + (size_t)(l + 32) * NRES;
        float u0 = p0[NQ] + p0[NQ + NH], v0 = p0[NQ] - p0[NQ + NH];
        float u1 = p1[NQ] + p1[NQ + NH], v1 = p1[NQ] - p1[NQ + NH];
        u64 pe0 = pk2(u0, u0), po0 = pk2(v0, v0);
        u64 pe1 = pk2(u1, u1), po1 = pk2(v1, v1);
        const ulonglong2* tp = (const ulonglong2*)&g_tw[NQ][0];
        #pragma unroll
        for (int m2 = 0; m2 < 4; ++m2) {
            ulonglong2 t = tp[m2];
            ffma2(acc[2 * m2],      t.x, pe0); ffma2(acc[2 * m2 + 1],  t.y, pe0);
            ffma2(acc[16 + 2 * m2], t.x, pe1); ffma2(acc[17 + 2 * m2], t.y, pe1);
        }
        #pragma unroll
        for (int m2 = 4; m2 < 8; ++m2) {
            ulonglong2 t = tp[m2];
            ffma2(acc[2 * m2],      t.x, po0); ffma2(acc[2 * m2 + 1],  t.y, po0);
            ffma2(acc[16 + 2 * m2], t.x, po1); ffma2(acc[17 + 2 * m2], t.y, po1);
        }
    }

    // cross-warp tree reduction, two 16-acc phases.
    // Scratch = SM[0..16K) (As/Bs region) — DISJOINT from uvq/twc (no race).
    u64* red = (u64*)SM;
    #pragma unroll
    for (int g = 0; g < 32; g += 16) {
        for (int half = 4; half > 0; half >>= 1) {
            if (w >= half && w < (half << 1)) {
                #pragma unroll
                for (int m = 0; m < 16; ++m)
                    red[((((w - half) << 4) + m) << 5) + l] = acc[g + m];
            }
            __syncthreads();
            if (w < half) {
                #pragma unroll
                for (int m = 0; m < 16; ++m)
                    fadd2(acc[g + m], red[(((w << 4) + m) << 5) + l]);
            }
            __syncthreads();
        }
    }
    if (w == 0) {
        u64* Xp = (u64*)&g_Xp[q][b][0][0];
        #pragma unroll
        for (int m = 0; m < 16; ++m) {
            Xp[l * 16 + m]        = acc[m];
            Xp[(l + 32) * 16 + m] = acc[16 + m];
        }
    }
}

// ------------------------------------------------------------------
// Kernel 3: sum 4 fwd partials + complex mode mix + irfft scale.
// ------------------------------------------------------------------
__global__ void __launch_bounds__(512) mix_kernel(const float* __restrict__ wr,
                                                  const float* __restrict__ wi) {
    __shared__ __align__(16) float2 Xs[CIN][MODES];   // 8 KB, slot order
    int b = blockIdx.x >> 1, oh = blockIdx.x & 1;
    int tid = threadIdx.x;
    const int STRIDE = BATCH * CIN * MODES;
    for (int t = tid; t < CIN * MODES; t += 512) {
        const float2* p = &((const float2*)g_Xp)[(size_t)b * CIN * MODES + t];
        float sx = 0.f, sy = 0.f;
        #pragma unroll
        for (int k = 0; k < 4; ++k) {
            float2 a = p[(size_t)k * STRIDE];
            sx += a.x; sy += a.y;
        }
        ((float2*)Xs)[t] = make_float2(sx, sy);
    }
    __syncthreads();
    int o = (oh << 5) + (tid >> 4), m = tid & 15, s = mslot(m);
    float yr = 0.f, yi = 0.f;
    #pragma unroll 4
    for (int i = 0; i < CIN; ++i) {
        float2 xv = Xs[i][s];
        float a = wr[(i * COUT + o) * MODES + m];
        float c = wi[(i * COUT + o) * MODES + m];
        yr = fmaf(xv.x, a, yr); yr = fmaf(-xv.y, c, yr);
        yi = fmaf(xv.x, c, yi); yi = fmaf(xv.y, a, yi);
    }
    float sc = (m == 0 ? 1.0f : 2.0f) * (1.0f / NRES);
    g_Y[b][o][s] = make_float2(yr * sc, yi * sc);
}

// ------------------------------------------------------------------
// Kernel 4: quarter-folded inverse, 2 n per thread (n0, n0+1).
// Grid 512 = (b:64, q:8), block 128, lb(128,4) -> one wave.
// 8 broadcast Y-LDS feed 32 ffma2; forward pair stores are STG.64.
// ------------------------------------------------------------------
__global__ void __launch_bounds__(128, 4) inv_kernel(float* __restrict__ out) {
    __shared__ __align__(16) u64 Ysh[COUT][MODES];   // 8 KB, slot order
    int b = blockIdx.x >> 3, q = blockIdx.x & 7;
    int tid = threadIdx.x;
    const u64* Yg = (const u64*)g_Y + (size_t)b * COUT * MODES;
    #pragma unroll
    for (int k = 0; k < 8; ++k) ((u64*)Ysh)[tid + k * 128] = Yg[tid + k * 128];
    __syncthreads();

    int n0 = (q << 8) + (tid << 1);                  // this thread: n0, n0+1
    u64 twA[16], twB[16];
    {
        const ulonglong2* tp = (const ulonglong2*)&g_tw[n0][0];
        #pragma unroll
        for (int m2 = 0; m2 < 8; ++m2) {
            ulonglong2 t = tp[m2];
            twA[2 * m2] = t.x; twA[2 * m2 + 1] = t.y;
        }
        tp = (const ulonglong2*)&g_tw[n0 + 1][0];
        #pragma unroll
        for (int m2 = 0; m2 < 8; ++m2) {
            ulonglong2 t = tp[m2];
            twB[2 * m2] = t.x; twB[2 * m2 + 1] = t.y;
        }
    }
    float* pb = out + (size_t)b * COUT * NRES;

    #pragma unroll 2
    for (int o = 0; o < COUT; ++o) {
        const ulonglong2* yp = (const ulonglong2*)&Ysh[o][0];
        u64 e0 = 0ull, od0 = 0ull, e1 = 0ull, od1 = 0ull;
        #pragma unroll
        for (int m2 = 0; m2 < 4; ++m2) {             // even slots
            ulonglong2 y = yp[m2];
            ffma2(e0, y.x, twA[2 * m2]); ffma2(e0, y.y, twA[2 * m2 + 1]);
            ffma2(e1, y.x, twB[2 * m2]); ffma2(e1, y.y, twB[2 * m2 + 1]);
        }
        #pragma unroll
        for (int m2 = 4; m2 < 8; ++m2) {             // odd slots
            ulonglong2 y = yp[m2];
            ffma2(od0, y.x, twA[2 * m2]); ffma2(od0, y.y, twA[2 * m2 + 1]);
            ffma2(od1, y.x, twB[2 * m2]); ffma2(od1, y.y, twB[2 * m2 + 1]);
        }
        float pe, qe, po, qo;
        upk2(e0,  pe, qe); float S0 = pe + qe, D0 = pe - qe;
        upk2(od0, po, qo); float T0 = po + qo, U0 = qo - po;
        upk2(e1,  pe, qe); float S1 = pe + qe, D1 = pe - qe;
        upk2(od1, po, qo); float T1 = po + qo, U1 = qo - po;
        float* p = pb + (size_t)o * NRES;
        *(float2*)(p + n0)      = make_float2(S0 + T0, S1 + T1);
        *(float2*)(p + n0 + NH) = make_float2(S0 - T0, S1 - T1);
        if (n0) {
            p[NH - n0]       = D0 + U0;
            p[NH - n0 - 1]   = D1 + U1;
            p[NRES - n0]     = D0 - U0;
            p[NRES - n0 - 1] = D1 - U1;
        } else {                                     // n=0 has no mirror; n=1 does
            p[NH - 1]   = D1 + U1;
            p[NRES - 1] = D1 - U1;
        }
    }

    // self-paired n=2048 outputs — q==0, one o per thread
    if (q == 0 && tid < COUT) {
        int o = tid;
        const ulonglong2* tp = (const ulonglong2*)&g_tw[NQ][0];
        const ulonglong2* yp = (const ulonglong2*)&Ysh[o][0];
        u64 e = 0ull, od = 0ull;
        #pragma unroll
        for (int m2 = 0; m2 < 4; ++m2) {
            ulonglong2 t = tp[m2]; ulonglong2 y = yp[m2];
            ffma2(e, y.x, t.x); ffma2(e, y.y, t.y);
        }
        #pragma unroll
        for (int m2 = 4; m2 < 8; ++m2) {
            ulonglong2 t = tp[m2]; ulonglong2 y = yp[m2];
            ffma2(od, y.x, t.x); ffma2(od, y.y, t.y);
        }
        float pe, qe, po, qo;
        upk2(e, pe, qe); upk2(od, po, qo);
        float E = pe + qe, O = po + qo;
        float* p = pb + (size_t)o * NRES;
        p[NQ]      = E + O;
        p[NQ + NH] = E - O;
    }
}

// ------------------------------------------------------------------
extern "C" void kernel_launch(void* const* d_in, const int* in_sizes, int n_in,
                              void* d_out, int out_size) {
    (void)in_sizes; (void)n_in; (void)out_size;
    const float* x  = (const float*)d_in[0];   // [64,64,8192]
    const float* wr = (const float*)d_in[1];   // [64,64,16]
    const float* wi = (const float*)d_in[2];   // [64,64,16]
    float* out = (float*)d_out;                // [64,64,8192]

    tw_kernel <<<129, 256>>>();
    fwd_kernel<<<256, 256>>>(x);
    mix_kernel<<<128, 512>>>(wr, wi);
    inv_kernel<<<512, 128>>>(out);
}